// round 15
// baseline (speedup 1.0000x reference)
#include <cuda_runtime.h>
#include <math.h>

#define MARGIN 0.2f
#define EPS_V  1e-6f
#define NLBL   256
#define MAXB   8192
#define INF_I  0x7fffffff

// Packed accumulator: bits[0:38) sum_q (fixed-point 2^16),
//                     bits[38:52) valid count, bits[52:64) done-block count.
#define CNT_SHIFT  38
#define DONE_SHIFT 52
#define SUM_MASK   ((1ull << CNT_SHIFT) - 1ull)
#define CNT_MASK   ((1ull << (DONE_SHIFT - CNT_SHIFT)) - 1ull)

// Only global state: zero-init at load; last block resets it each run.
__device__ unsigned long long g_acc;

// Deterministic per-row quantization (order-independent integer sums).
__device__ __forceinline__ unsigned long long quant(float per) {
    return (unsigned long long)(unsigned int)(per * 65536.0f + 0.5f);
}

// ---------------------------------------------------------------------------
// Warp-collective: first j with label[j]==lab_i && zidx[j]!=idx_i (or -1).
// Rare/slow path only.
// ---------------------------------------------------------------------------
__device__ __forceinline__ int warp_find_pos(const int* __restrict__ label,
                                             const int* __restrict__ zidx,
                                             int B, int lane, int lab_i, int idx_i) {
    for (int base = 0; base < B; base += 128) {
        const int j0 = base + (lane << 2);
        unsigned sub = 0u;
        if (j0 + 3 < B) {
            int4 lv = *(const int4*)(label + j0);
            sub = (lv.x == lab_i ? 1u : 0u) | (lv.y == lab_i ? 2u : 0u)
                | (lv.z == lab_i ? 4u : 0u) | (lv.w == lab_i ? 8u : 0u);
        } else {
            #pragma unroll
            for (int t = 0; t < 4; t++) {
                int j = j0 + t;
                if (j < B && label[j] == lab_i) sub |= 1u << t;
            }
        }
        while (true) {
            unsigned act = __ballot_sync(0xffffffffu, sub != 0u);
            if (!act) break;
            int src = __ffs(act) - 1;
            unsigned ssub = __shfl_sync(0xffffffffu, sub, src);
            int j = base + (src << 2) + (__ffs(ssub) - 1);
            if (__ldg(&zidx[j]) != idx_i) return j;
            if (lane == src) sub &= (sub - 1u);
        }
    }
    return -1;
}

// Generic distance (LDG loops), any C.
__device__ __forceinline__ float row_loss_generic(const float* __restrict__ z,
                                                  int C, int lane,
                                                  int i, int pos, int neg) {
    const float4* a = (const float4*)(z + (size_t)i * C);
    const float4* p = (const float4*)(z + (size_t)pos * C);
    const float4* n = (const float4*)(z + (size_t)neg * C);
    float sap = 0.0f, san = 0.0f;
    const int nvec = C >> 2;
    for (int v = lane; v < nvec; v += 32) {
        float4 avv = a[v];
        float4 pv = __ldg(&p[v]);
        float4 nv = __ldg(&n[v]);
        float d;
        d = avv.x - pv.x + EPS_V; sap = fmaf(d, d, sap);
        d = avv.y - pv.y + EPS_V; sap = fmaf(d, d, sap);
        d = avv.z - pv.z + EPS_V; sap = fmaf(d, d, sap);
        d = avv.w - pv.w + EPS_V; sap = fmaf(d, d, sap);
        d = avv.x - nv.x + EPS_V; san = fmaf(d, d, san);
        d = avv.y - nv.y + EPS_V; san = fmaf(d, d, san);
        d = avv.z - nv.z + EPS_V; san = fmaf(d, d, san);
        d = avv.w - nv.w + EPS_V; san = fmaf(d, d, san);
    }
    for (int t = C & 3, base = C & ~3; t > 0; t--) {  // C%4 tail (scalar, lane 0)
        if (lane == 0) {
            int c = base + t - 1;
            float d1 = z[(size_t)i * C + c] - z[(size_t)pos * C + c] + EPS_V;
            float d2 = z[(size_t)i * C + c] - z[(size_t)neg * C + c] + EPS_V;
            sap = fmaf(d1, d1, sap); san = fmaf(d2, d2, san);
        }
    }
    #pragma unroll
    for (int o = 16; o > 0; o >>= 1) {
        sap += __shfl_xor_sync(0xffffffffu, sap, o);
        san += __shfl_xor_sync(0xffffffffu, san, o);
    }
    return fmaxf(sqrtf(sap) - sqrtf(san) + MARGIN, 0.0f);
}

// ---------------------------------------------------------------------------
// One block per label value (grid = 256). Scan -> member list + f + mfirst;
// stage pos row f and neg row in SMEM; stream member a-rows with a depth-2
// register pipeline. Hot loop: a from regs, p and n from LDS — no global
// loads besides the a-stream. Fallback (allsame / C!=1024 / B>MAXB): rows
// strided over all 2048 warps, R11-style.
// ---------------------------------------------------------------------------
__global__ void __launch_bounds__(256) triplet_kernel(const float* __restrict__ z,
                                                      const int* __restrict__ label,
                                                      const int* __restrict__ zidx,
                                                      float* __restrict__ out,
                                                      int B, int C, int k) {
    __shared__ int    s_members[MAXB];
    __shared__ int    s_cnt, s_f, s_s2, s_mf;
    __shared__ float4 s_p4[256];
    __shared__ float4 s_n4[256];
    __shared__ unsigned long long s_q[8];
    __shared__ unsigned int s_c[8];

    const int tid  = threadIdx.x;
    const int warp = tid >> 5;
    const int lane = tid & 31;
    const int L    = blockIdx.x;

    if (tid == 0) { s_cnt = 0; s_f = INF_I; s_s2 = INF_I; s_mf = INF_I; }
    __syncthreads();
    const int l0 = __ldg(&label[0]);

    // ---- scan all labels: members of L, min member, first j!=l0 ----
    int my_mf = INF_I, my_f = INF_I;
    const int nv4 = B >> 2;
    const int4* lab4 = (const int4*)label;
    for (int v = tid; v < nv4; v += 256) {
        int4 lv = lab4[v];
        const int j = v << 2;
        if (lv.x == L) { int m = atomicAdd(&s_cnt, 1); if (m < MAXB) s_members[m] = j;     my_f = min(my_f, j); }
        if (lv.y == L) { int m = atomicAdd(&s_cnt, 1); if (m < MAXB) s_members[m] = j + 1; my_f = min(my_f, j + 1); }
        if (lv.z == L) { int m = atomicAdd(&s_cnt, 1); if (m < MAXB) s_members[m] = j + 2; my_f = min(my_f, j + 2); }
        if (lv.w == L) { int m = atomicAdd(&s_cnt, 1); if (m < MAXB) s_members[m] = j + 3; my_f = min(my_f, j + 3); }
        if (lv.x != l0) my_mf = min(my_mf, j);
        if (lv.y != l0) my_mf = min(my_mf, j + 1);
        if (lv.z != l0) my_mf = min(my_mf, j + 2);
        if (lv.w != l0) my_mf = min(my_mf, j + 3);
    }
    for (int j = (nv4 << 2) + tid; j < B; j += 256) {
        int lb = label[j];
        if (lb == L)  { int m = atomicAdd(&s_cnt, 1); if (m < MAXB) s_members[m] = j; my_f = min(my_f, j); }
        if (lb != l0) my_mf = min(my_mf, j);
    }
    #pragma unroll
    for (int o = 16; o > 0; o >>= 1) {
        my_mf = min(my_mf, __shfl_xor_sync(0xffffffffu, my_mf, o));
        my_f  = min(my_f,  __shfl_xor_sync(0xffffffffu, my_f,  o));
    }
    if (lane == 0) { atomicMin(&s_mf, my_mf); atomicMin(&s_f, my_f); }
    __syncthreads();

    const bool allsame  = (s_mf == INF_I);
    const bool fastpath = (!allsame) && (C == 1024) && (B <= MAXB);

    unsigned long long wq = 0ull;
    unsigned int       wc = 0u;

    if (fastpath) {
        const int cnt = s_cnt;
        if (cnt > 0) {
            const int f = s_f;
            // second occurrence (min member != f)
            int my_s2 = INF_I;
            for (int m = tid; m < cnt; m += 256) {
                int j = s_members[m];
                if (j != f) my_s2 = min(my_s2, j);
            }
            #pragma unroll
            for (int o = 16; o > 0; o >>= 1)
                my_s2 = min(my_s2, __shfl_xor_sync(0xffffffffu, my_s2, o));
            if (lane == 0) atomicMin(&s_s2, my_s2);

            const int neg = (L != l0) ? 0 : s_mf;
            // stage pos row f and neg row (1 float4 per thread each)
            s_p4[tid] = __ldg(&((const float4*)(z + (size_t)f   * 1024))[tid]);
            s_n4[tid] = __ldg(&((const float4*)(z + (size_t)neg * 1024))[tid]);
            __syncthreads();

            const int idxf = __ldg(&zidx[f]);

            // ---- member loop, depth-2 register pipeline ----
            int mi = warp;
            int iA = (mi < cnt) ? s_members[mi] : -1;
            float4 avA[8];
            if (iA >= 0) {
                const float4* a = (const float4*)(z + (size_t)iA * 1024);
                #pragma unroll
                for (int u = 0; u < 8; u++) avA[u] = a[lane + (u << 5)];
            }
            while (iA >= 0) {
                const int miN = mi + 8;
                const int iB = (miN < cnt) ? s_members[miN] : -1;
                float4 avB[8];
                if (iB >= 0) {
                    const float4* a = (const float4*)(z + (size_t)iB * 1024);
                    #pragma unroll
                    for (int u = 0; u < 8; u++) avB[u] = a[lane + (u << 5)];
                }

                const int idxi = __ldg(&zidx[iA]);
                float per = -1.0f;
                if (iA != f && idxf != idxi) {
                    // hot path: p and n both from SMEM
                    float sap = 0.0f, san = 0.0f;
                    #pragma unroll
                    for (int u = 0; u < 8; u++) {
                        const int v = lane + (u << 5);
                        float4 pv = s_p4[v];
                        float4 nv = s_n4[v];
                        float d;
                        d = avA[u].x - pv.x + EPS_V; sap = fmaf(d, d, sap);
                        d = avA[u].y - pv.y + EPS_V; sap = fmaf(d, d, sap);
                        d = avA[u].z - pv.z + EPS_V; sap = fmaf(d, d, sap);
                        d = avA[u].w - pv.w + EPS_V; sap = fmaf(d, d, sap);
                        d = avA[u].x - nv.x + EPS_V; san = fmaf(d, d, san);
                        d = avA[u].y - nv.y + EPS_V; san = fmaf(d, d, san);
                        d = avA[u].z - nv.z + EPS_V; san = fmaf(d, d, san);
                        d = avA[u].w - nv.w + EPS_V; san = fmaf(d, d, san);
                    }
                    #pragma unroll
                    for (int o = 16; o > 0; o >>= 1) {
                        sap += __shfl_xor_sync(0xffffffffu, sap, o);
                        san += __shfl_xor_sync(0xffffffffu, san, o);
                    }
                    per = fmaxf(sqrtf(sap) - sqrtf(san) + MARGIN, 0.0f);
                } else {
                    // rare: i is the first occurrence (or zidx degenerate)
                    int pos = warp_find_pos(label, zidx, B, lane, L, idxi);
                    if (pos >= 0) {
                        const float4* p = (const float4*)(z + (size_t)pos * 1024);
                        float sap = 0.0f, san = 0.0f;
                        #pragma unroll
                        for (int u = 0; u < 8; u++) {
                            const int v = lane + (u << 5);
                            float4 pv = __ldg(&p[v]);
                            float4 nv = s_n4[v];
                            float d;
                            d = avA[u].x - pv.x + EPS_V; sap = fmaf(d, d, sap);
                            d = avA[u].y - pv.y + EPS_V; sap = fmaf(d, d, sap);
                            d = avA[u].z - pv.z + EPS_V; sap = fmaf(d, d, sap);
                            d = avA[u].w - pv.w + EPS_V; sap = fmaf(d, d, sap);
                            d = avA[u].x - nv.x + EPS_V; san = fmaf(d, d, san);
                            d = avA[u].y - nv.y + EPS_V; san = fmaf(d, d, san);
                            d = avA[u].z - nv.z + EPS_V; san = fmaf(d, d, san);
                            d = avA[u].w - nv.w + EPS_V; san = fmaf(d, d, san);
                        }
                        #pragma unroll
                        for (int o = 16; o > 0; o >>= 1) {
                            sap += __shfl_xor_sync(0xffffffffu, sap, o);
                            san += __shfl_xor_sync(0xffffffffu, san, o);
                        }
                        per = fmaxf(sqrtf(sap) - sqrtf(san) + MARGIN, 0.0f);
                    }
                }
                if (per >= 0.0f) { wq += quant(per); wc++; }

                #pragma unroll
                for (int u = 0; u < 8; u++) avA[u] = avB[u];
                iA = iB; mi = miN;
            }
        }
    } else {
        // ---- fallback: rows strided over all 256 blocks x 8 warps ----
        for (int i = blockIdx.x * 8 + warp; i < B; i += NLBL * 8) {
            const int lab_i = __ldg(&label[i]);
            const int idx_i = __ldg(&zidx[i]);
            int pos = -1, neg = -1;
            if (!allsame) {
                neg = (lab_i != l0) ? 0 : s_mf;
                pos = warp_find_pos(label, zidx, B, lane, lab_i, idx_i);
            } else {
                if (i < k) { pos = (i == 0) ? 1 : 0;       neg = k; }
                else       { pos = (i == k) ? (k + 1) : k; neg = 0; }
                if (pos >= B || neg >= B || k < 2) pos = -1;
            }
            if (pos >= 0 && neg >= 0 && neg < B) {
                float per = row_loss_generic(z, C, lane, i, pos, neg);
                wq += quant(per); wc++;
            }
        }
    }

    // ---- single-atomic deterministic tail ----
    if (lane == 0) { s_q[warp] = wq; s_c[warp] = wc; }
    __syncthreads();
    if (tid == 0) {
        unsigned long long q = 0ull; unsigned int c = 0u;
        #pragma unroll
        for (int w = 0; w < 8; w++) { q += s_q[w]; c += s_c[w]; }
        unsigned long long val = q
                               | ((unsigned long long)c << CNT_SHIFT)
                               | (1ull << DONE_SHIFT);
        unsigned long long old = atomicAdd(&g_acc, val);   // relaxed, no fence
        if ((old >> DONE_SHIFT) == (unsigned long long)(NLBL - 1)) {
            unsigned long long t = old + val;
            unsigned long long sq = t & SUM_MASK;
            unsigned int cc = (unsigned int)((t >> CNT_SHIFT) & CNT_MASK);
            out[0] = (cc > 0u) ? (float)(((double)sq / 65536.0) / (double)cc) : 0.0f;
            g_acc = 0ull;   // reset for next graph replay
        }
    }
}

extern "C" void kernel_launch(void* const* d_in, const int* in_sizes, int n_in,
                              void* d_out, int out_size) {
    const int* z_label = (const int*)d_in[0];
    const int* z_idx   = (const int*)d_in[1];
    const float* z     = (const float*)d_in[2];
    float* out = (float*)d_out;

    const int B = in_sizes[0];
    const int C = in_sizes[2] / B;
    int k = (int)((double)B * 0.01);
    if (k < 2) k = 2;

    triplet_kernel<<<NLBL, 256>>>(z, z_label, z_idx, out, B, C, k);
}